// round 1
// baseline (speedup 1.0000x reference)
#include <cuda_runtime.h>
#include <math.h>

#define BB 2
#define CC 128
#define HH 128
#define WW 128
#define NPIX (HH*WW)
#define HTH 184
#define HTW 180
#define NBINS (HTH*HTW)      // 33120
#define NSPH 16384
#define KHT 8
#define KSPH 16
#define NN0 1024
#define NN1 256
#define NN2 64
#define EPS_F 1e-5f
#define M_CONV (BB*NBINS)    // 66240
#define NCHUNK 240
#define ROWS_PER_CHUNK (M_CONV/NCHUNK)  // 276

// ---------------- scratch (static device memory; no runtime allocation) ----------------
__device__ float g_xt[BB*NPIX*CC];        // post-BN ReLU image, [b][pix][c]
__device__ float g_ht[BB*NBINS*CC];       // hough output, [b][bin][c] (NHWC for conv)
__device__ float g_hc[BB*NBINS*CC];       // conv output
__device__ float g_scale[CC], g_bias[CC];     // image BN fold
__device__ float g_cscale[CC], g_cbias[CC];   // conv BN fold
__device__ float g_psum[NCHUNK*CC], g_psq[NCHUNK*CC];
__device__ float g_s0[BB*NN0*CC], g_s1[BB*3*NN1*CC], g_s2[BB*3*NN2*CC];
__device__ float g_y0[BB*NN0*64], g_y1[BB*3*NN1*64], g_y2[BB*3*NN2*64];
__device__ float g_tmp[BB*NN0*64];
__device__ float g_logit[BB*NN0 + BB*3*NN1 + BB*3*NN2];   // 2048 + 1536 + 384

// ---------------- 1) image BN stats ----------------
__global__ void k_img_stats(const float* __restrict__ img,
                            const float* __restrict__ gamma,
                            const float* __restrict__ beta) {
    int c = blockIdx.x;
    float s = 0.f, q = 0.f;
    for (int i = threadIdx.x; i < BB*NPIX; i += blockDim.x) {
        int b = i >> 14;           // / NPIX
        int p = i & (NPIX-1);
        float v = img[(b*CC + c)*NPIX + p];
        s += v; q += v*v;
    }
    __shared__ float ss[256], sq[256];
    ss[threadIdx.x] = s; sq[threadIdx.x] = q;
    __syncthreads();
    for (int st = 128; st > 0; st >>= 1) {
        if (threadIdx.x < st) { ss[threadIdx.x] += ss[threadIdx.x+st]; sq[threadIdx.x] += sq[threadIdx.x+st]; }
        __syncthreads();
    }
    if (threadIdx.x == 0) {
        float inv = 1.f/(BB*NPIX);
        float m = ss[0]*inv;
        float var = sq[0]*inv - m*m;
        float r = rsqrtf(var + EPS_F);
        g_scale[c] = gamma[c]*r;
        g_bias[c]  = beta[c] - gamma[c]*m*r;
    }
}

// ---------------- 2) BN + ReLU + transpose to [b][pix][c] ----------------
__global__ void k_bn_transpose(const float* __restrict__ img) {
    __shared__ float tile[32][33];
    int p0 = blockIdx.x*32, c0 = blockIdx.y*32, b = blockIdx.z;
    #pragma unroll
    for (int j = 0; j < 4; j++) {
        int c = c0 + threadIdx.y + j*8;
        tile[threadIdx.y + j*8][threadIdx.x] = img[(b*CC + c)*NPIX + p0 + threadIdx.x];
    }
    __syncthreads();
    #pragma unroll
    for (int j = 0; j < 4; j++) {
        int p = p0 + threadIdx.y + j*8;
        int c = c0 + threadIdx.x;
        float v = g_scale[c]*tile[threadIdx.x][threadIdx.y + j*8] + g_bias[c];
        g_xt[((size_t)b*NPIX + p)*CC + c] = fmaxf(v, 0.f);
    }
}

// ---------------- 3) Hough gather ----------------
__global__ void k_hough(const int* __restrict__ ht_idx, const float* __restrict__ ht_w) {
    int bin = blockIdx.x, b = blockIdx.y, c = threadIdx.x;
    const float* xb = g_xt + (size_t)b*NPIX*CC;
    float acc = 0.f;
    #pragma unroll
    for (int k = 0; k < KHT; k++) {
        int p = __ldg(&ht_idx[bin*KHT + k]);
        float w = __ldg(&ht_w[bin*KHT + k]);
        acc += w * xb[p*CC + c];
    }
    g_ht[((size_t)b*NBINS + bin)*CC + c] = acc;
}

// ---------------- 4) 3x3 conv as implicit GEMM (fp32, 64x128 tile) ----------------
#define BM 64
#define BN 128
#define BK 16
__global__ void __launch_bounds__(256) k_conv(const float* __restrict__ Wt) {
    __shared__ float As[BK][BM+4];   // [k][m], +4 pad keeps 16B alignment per row
    __shared__ float Bs[BK][BN];
    int m0 = blockIdx.x*BM;
    int tid = threadIdx.x;
    int tm = (tid >> 4)*4;           // 0..60
    int tn = (tid & 15)*8;           // 0..120
    float acc[4][8];
    #pragma unroll
    for (int i = 0; i < 4; i++)
        #pragma unroll
        for (int j = 0; j < 8; j++) acc[i][j] = 0.f;

    // A loader: row lm, k-segment lseg
    int lm = tid >> 2, lseg = (tid & 3)*4;
    int s  = m0 + lm;
    int sb = s / NBINS; int sr = s - sb*NBINS;
    int sh = sr / HTW;  int sw = sr - sh*HTW;
    // B loader
    int lkb = tid >> 4, lcb = (tid & 15)*8;

    for (int r = 0; r < 9; r++) {
        int dy = r/3 - 1, dx = r%3 - 1;
        int h2 = sh + dy, w2 = sw + dx;
        bool valid = ((unsigned)h2 < HTH) && ((unsigned)w2 < HTW);
        const float* arow = g_ht + (((size_t)sb*NBINS) + h2*HTW + w2)*CC;
        const float* brow = Wt + (size_t)r*CC*CC;
        for (int kk = 0; kk < CC; kk += BK) {
            float4 av = make_float4(0.f,0.f,0.f,0.f);
            if (valid) av = *(const float4*)(arow + kk + lseg);
            As[lseg+0][lm]=av.x; As[lseg+1][lm]=av.y; As[lseg+2][lm]=av.z; As[lseg+3][lm]=av.w;
            const float* bp = brow + (kk + lkb)*CC + lcb;
            *(float4*)&Bs[lkb][lcb]   = *(const float4*)bp;
            *(float4*)&Bs[lkb][lcb+4] = *(const float4*)(bp+4);
            __syncthreads();
            #pragma unroll
            for (int k = 0; k < BK; k++) {
                float4 a4 = *(const float4*)&As[k][tm];
                float4 b0 = *(const float4*)&Bs[k][tn];
                float4 b1 = *(const float4*)&Bs[k][tn+4];
                float a[4] = {a4.x, a4.y, a4.z, a4.w};
                float bb[8] = {b0.x,b0.y,b0.z,b0.w,b1.x,b1.y,b1.z,b1.w};
                #pragma unroll
                for (int i = 0; i < 4; i++)
                    #pragma unroll
                    for (int j = 0; j < 8; j++)
                        acc[i][j] += a[i]*bb[j];
            }
            __syncthreads();
        }
    }
    #pragma unroll
    for (int i = 0; i < 4; i++) {
        size_t m = (size_t)(m0 + tm + i);
        float* cp = g_hc + m*CC + tn;
        float4 o0 = make_float4(acc[i][0],acc[i][1],acc[i][2],acc[i][3]);
        float4 o1 = make_float4(acc[i][4],acc[i][5],acc[i][6],acc[i][7]);
        *(float4*)cp = o0; *(float4*)(cp+4) = o1;
    }
}

// ---------------- 5) conv BN stats (deterministic 2-stage) ----------------
__global__ void k_conv_stats1() {
    int chunk = blockIdx.x, c = threadIdx.x;
    size_t r0 = (size_t)chunk * ROWS_PER_CHUNK;
    float s = 0.f, q = 0.f;
    for (int i = 0; i < ROWS_PER_CHUNK; i++) {
        float v = g_hc[(r0 + i)*CC + c];
        s += v; q += v*v;
    }
    g_psum[chunk*CC + c] = s;
    g_psq[chunk*CC + c]  = q;
}
__global__ void k_conv_stats2(const float* __restrict__ gamma, const float* __restrict__ beta) {
    int c = threadIdx.x;
    float s = 0.f, q = 0.f;
    for (int i = 0; i < NCHUNK; i++) { s += g_psum[i*CC + c]; q += g_psq[i*CC + c]; }
    float inv = 1.f/(float)M_CONV;
    float m = s*inv;
    float var = q*inv - m*m;
    float r = rsqrtf(var + EPS_F);
    g_cscale[c] = gamma[c]*r;
    g_cbias[c]  = beta[c] - gamma[c]*m*r;
}

// ---------------- 6) sphere gather (fused conv-BN+ReLU) ----------------
__global__ void k_sphere(const int* __restrict__ ind, const int* __restrict__ sph_idx,
                         const float* __restrict__ sph_w, float* __restrict__ out, int S) {
    int j = blockIdx.x, b = blockIdx.y, c = threadIdx.x;
    int v = __ldg(&ind[b*S + j]);
    const float* hc = g_hc + (size_t)b*NBINS*CC;
    float sc = g_cscale[c], bi = g_cbias[c];
    float acc = 0.f;
    #pragma unroll
    for (int k = 0; k < KSPH; k++) {
        int bin = __ldg(&sph_idx[v*KSPH + k]);
        float w = __ldg(&sph_w[v*KSPH + k]);
        float x = sc*hc[(size_t)bin*CC + c] + bi;
        acc += w * fmaxf(x, 0.f);
    }
    out[((size_t)b*S + j)*CC + c] = acc;
}

// ---------------- 7) sconv: 1x1 conv 128->64 + bias ----------------
#define SC_ROWS 16
__global__ void k_sconv(const float* __restrict__ x, const float* __restrict__ w,
                        const float* __restrict__ bias, float* __restrict__ y, int M) {
    __shared__ float Ws[128*64];   // [c][o]
    __shared__ float xr[128];
    int o = threadIdx.x;
    for (int i = o; i < 128*64; i += 64) {
        int oo = i >> 7, ci = i & 127;
        Ws[ci*64 + oo] = w[i];
    }
    float bo = bias[o];
    __syncthreads();
    int r0 = blockIdx.x * SC_ROWS;
    for (int rr = 0; rr < SC_ROWS; rr++) {
        int m = r0 + rr;
        xr[o]    = x[(size_t)m*128 + o];
        xr[o+64] = x[(size_t)m*128 + 64 + o];
        __syncthreads();
        float acc = bo;
        #pragma unroll 8
        for (int c = 0; c < 128; c++) acc += xr[c]*Ws[c*64 + o];
        y[(size_t)m*64 + o] = acc;
        __syncthreads();
    }
}

// ---------------- 7b) sconv BN stats + apply ----------------
__global__ void k_sconv_stats(const float* __restrict__ y, const float* __restrict__ gamma,
                              const float* __restrict__ beta, float* __restrict__ scs,
                              float* __restrict__ scb, int M) {
    int o = threadIdx.x;
    float s = 0.f, q = 0.f;
    for (int m = 0; m < M; m++) { float v = y[(size_t)m*64 + o]; s += v; q += v*v; }
    float inv = 1.f/(float)M;
    float mn = s*inv;
    float var = q*inv - mn*mn;
    float r = rsqrtf(var + EPS_F);
    scs[o] = gamma[o]*r;
    scb[o] = beta[o] - gamma[o]*mn*r;
}
__device__ float g_scs[64], g_scb[64];
__global__ void k_bnrelu64(float* __restrict__ y, int total) {
    int i = blockIdx.x*blockDim.x + threadIdx.x;
    if (i < total) {
        int o = i & 63;
        y[i] = fmaxf(g_scs[o]*y[i] + g_scb[o], 0.f);
    }
}

// ---------------- 8) EdgeConv layer (4 nodes in parallel, 4 iters/block) ----------------
#define EC_SLOTS 4
#define EC_ITERS 4
__global__ void __launch_bounds__(256) k_edgeconv(
        const float* __restrict__ x, float* __restrict__ xo, const int* __restrict__ edge,
        const float* __restrict__ w, const float* __restrict__ bias, int n, int kn) {
    __shared__ float Ws[128*64];   // same [c][o] layout as given
    __shared__ float xcs[EC_SLOTS][64], ds[EC_SLOTS][64];
    __shared__ float bsm[64];
    int slot = threadIdx.x >> 6, o = threadIdx.x & 63;
    for (int i = threadIdx.x; i < 128*64; i += 256) Ws[i] = w[i];
    if (threadIdx.x < 64) bsm[threadIdx.x] = bias[threadIdx.x];
    int bg = blockIdx.y;
    const float* xb = x + (size_t)bg*n*64;
    const int* ec = edge + (size_t)bg*2*n*kn;
    const int* en = ec + n*kn;
    __syncthreads();
    for (int it = 0; it < EC_ITERS; it++) {
        int j = blockIdx.x*(EC_SLOTS*EC_ITERS) + it*EC_SLOTS + slot;
        float mx = -1e30f;
        for (int kk = 0; kk < kn; kk++) {
            int e = j*kn + kk;
            int ci = __ldg(&ec[e]), ni = __ldg(&en[e]);
            __syncthreads();
            float xc = xb[(size_t)ci*64 + o];
            xcs[slot][o] = xc;
            ds[slot][o]  = xb[(size_t)ni*64 + o] - xc;
            __syncthreads();
            float acc = bsm[o];
            #pragma unroll 8
            for (int c = 0; c < 64; c++)
                acc += xcs[slot][c]*Ws[c*64 + o] + ds[slot][c]*Ws[(64+c)*64 + o];
            mx = fmaxf(mx, fmaxf(acc, 0.f));
        }
        xo[(size_t)bg*n*64 + (size_t)j*64 + o] = mx;
    }
}

// ---------------- 9) head: logits = x @ hw + hb ----------------
__global__ void k_head(const float* __restrict__ x, const float* __restrict__ hw,
                       const float* __restrict__ hb, float* __restrict__ logit, int total) {
    int gw = (blockIdx.x*blockDim.x + threadIdx.x) >> 5;
    int lane = threadIdx.x & 31;
    if (gw >= total) return;
    float a = x[(size_t)gw*64 + lane]*hw[lane] + x[(size_t)gw*64 + 32 + lane]*hw[32 + lane];
    #pragma unroll
    for (int s2 = 16; s2 > 0; s2 >>= 1) a += __shfl_down_sync(0xffffffffu, a, s2);
    if (lane == 0) logit[gw] = a + hb[0];
}

// ---------------- 10) BCE ----------------
__global__ void k_bce(const float* __restrict__ logit, const int* __restrict__ target,
                      float* __restrict__ out, int M, int outIdx) {
    float sp = 0.f, sn = 0.f; float cp = 0.f, cn = 0.f;
    for (int i = threadIdx.x; i < M; i += 256) {
        float z = logit[i];
        float t = (float)target[i];
        float l = fmaxf(z, 0.f) - z*t + log1pf(expf(-fabsf(z)));
        if (t > 0.5f) { sp += l; cp += 1.f; } else { sn += l; cn += 1.f; }
    }
    __shared__ float r0[256], r1[256], r2[256], r3[256];
    r0[threadIdx.x]=sp; r1[threadIdx.x]=sn; r2[threadIdx.x]=cp; r3[threadIdx.x]=cn;
    __syncthreads();
    for (int st = 128; st > 0; st >>= 1) {
        if (threadIdx.x < st) {
            r0[threadIdx.x]+=r0[threadIdx.x+st]; r1[threadIdx.x]+=r1[threadIdx.x+st];
            r2[threadIdx.x]+=r2[threadIdx.x+st]; r3[threadIdx.x]+=r3[threadIdx.x+st];
        }
        __syncthreads();
    }
    if (threadIdx.x == 0) {
        out[outIdx]   = r0[0] / fmaxf(r2[0], 1.f);
        out[outIdx+1] = r1[0] / fmaxf(r3[0], 1.f);
    }
}

// ---------------- 11) preds ----------------
__global__ void k_preds(float* __restrict__ out) {
    int i = blockIdx.x*blockDim.x + threadIdx.x;
    if (i >= 3968) return;
    float z; int b, col;
    if (i < 2048) {
        b = i >> 10; col = i & 1023;
        z = g_logit[i];
    } else if (i < 3584) {
        int m = i - 2048;
        int bg = m >> 8, j = m & 255;
        b = bg/3; int v = bg - b*3;
        col = 1024 + v*256 + j;
        z = g_logit[2048 + m];
    } else {
        int m = i - 3584;
        int bg = m >> 6, j = m & 63;
        b = bg/3; int v = bg - b*3;
        col = 1792 + v*64 + j;
        z = g_logit[3584 + m];
    }
    out[6 + b*1984 + col] = 1.f/(1.f + expf(-z));
}

// ---------------- launch ----------------
extern "C" void kernel_launch(void* const* d_in, const int* in_sizes, int n_in,
                              void* d_out, int out_size) {
    const float* image     = (const float*)d_in[0];
    const float* bn_gamma  = (const float*)d_in[1];
    const float* bn_beta   = (const float*)d_in[2];
    const int*   ht_idx    = (const int*)  d_in[3];
    const float* ht_w      = (const float*)d_in[4];
    const float* w_htconv  = (const float*)d_in[5];
    const float* htbn_g    = (const float*)d_in[6];
    const float* htbn_b    = (const float*)d_in[7];
    const int*   sph_idx   = (const int*)  d_in[8];
    const float* sph_w     = (const float*)d_in[9];
    const float* w_sc      = (const float*)d_in[10];
    const float* b_sc      = (const float*)d_in[11];
    const float* scbn_g    = (const float*)d_in[12];
    const float* scbn_b    = (const float*)d_in[13];
    const float* dgcn_w    = (const float*)d_in[14];
    const float* dgcn_b    = (const float*)d_in[15];
    const float* dgcn_hw   = (const float*)d_in[16];
    const float* dgcn_hb   = (const float*)d_in[17];
    const int*   ind0      = (const int*)  d_in[18];
    const int*   ind1      = (const int*)  d_in[19];
    const int*   ind2      = (const int*)  d_in[20];
    const int*   edge0     = (const int*)  d_in[21];
    const int*   edge1     = (const int*)  d_in[22];
    const int*   edge2     = (const int*)  d_in[23];
    const int*   target0   = (const int*)  d_in[24];
    const int*   target1   = (const int*)  d_in[25];
    const int*   target2   = (const int*)  d_in[26];
    float* out = (float*)d_out;

    // stage A: image BN + transpose
    k_img_stats<<<CC, 256>>>(image, bn_gamma, bn_beta);
    k_bn_transpose<<<dim3(NPIX/32, CC/32, BB), dim3(32,8)>>>(image);

    // stage B: hough
    k_hough<<<dim3(NBINS, BB), CC>>>(ht_idx, ht_w);

    // stage C: conv (implicit GEMM)
    k_conv<<<M_CONV/BM, 256>>>(w_htconv);
    k_conv_stats1<<<NCHUNK, CC>>>();
    k_conv_stats2<<<1, CC>>>(htbn_g, htbn_b);

    // stage D: sphere gathers (fused BN+ReLU of conv output)
    float* g_s0p; cudaGetSymbolAddress((void**)&g_s0p, g_s0);
    float* g_s1p; cudaGetSymbolAddress((void**)&g_s1p, g_s1);
    float* g_s2p; cudaGetSymbolAddress((void**)&g_s2p, g_s2);
    float* g_y0p; cudaGetSymbolAddress((void**)&g_y0p, g_y0);
    float* g_y1p; cudaGetSymbolAddress((void**)&g_y1p, g_y1);
    float* g_y2p; cudaGetSymbolAddress((void**)&g_y2p, g_y2);
    float* g_tmpp; cudaGetSymbolAddress((void**)&g_tmpp, g_tmp);
    float* g_scsp; cudaGetSymbolAddress((void**)&g_scsp, g_scs);
    float* g_scbp; cudaGetSymbolAddress((void**)&g_scbp, g_scb);
    float* g_logitp; cudaGetSymbolAddress((void**)&g_logitp, g_logit);

    k_sphere<<<dim3(NN0,   BB), CC>>>(ind0, sph_idx, sph_w, g_s0p, NN0);
    k_sphere<<<dim3(3*NN1, BB), CC>>>(ind1, sph_idx, sph_w, g_s1p, 3*NN1);
    k_sphere<<<dim3(3*NN2, BB), CC>>>(ind2, sph_idx, sph_w, g_s2p, 3*NN2);

    const int M0 = BB*NN0, M1 = BB*3*NN1, M2 = BB*3*NN2;   // 2048, 1536, 384
    const float* srcS[3] = {g_s0p, g_s1p, g_s2p};
    float* ybuf[3] = {g_y0p, g_y1p, g_y2p};
    const int Ms[3] = {M0, M1, M2};

    for (int s = 0; s < 3; s++) {
        k_sconv<<<Ms[s]/SC_ROWS, 64>>>(srcS[s], w_sc + (size_t)s*64*128, b_sc + s*64, ybuf[s], Ms[s]);
        k_sconv_stats<<<1, 64>>>(ybuf[s], scbn_g + s*64, scbn_b + s*64, g_scsp, g_scbp, Ms[s]);
        k_bnrelu64<<<(Ms[s]*64 + 255)/256, 256>>>(ybuf[s], Ms[s]*64);

        // DGCN: 4 EdgeConv layers, ping-pong ybuf <-> g_tmp
        int n  = (s == 0) ? NN0 : (s == 1 ? NN1 : NN2);
        int bg = (s == 0) ? BB : BB*3;
        const int* eg = (s == 0) ? edge0 : (s == 1 ? edge1 : edge2);
        float* bufs[2] = {ybuf[s], g_tmpp};
        for (int L = 0; L < 4; L++) {
            const float* xin = bufs[L & 1];
            float* xout      = bufs[(L+1) & 1];
            k_edgeconv<<<dim3(n/(EC_SLOTS*EC_ITERS), bg), 256>>>(
                xin, xout, eg,
                dgcn_w + ((size_t)s*4 + L)*128*64,
                dgcn_b + ((size_t)s*4 + L)*64, n, 8);
        }
        // after 4 layers result is back in ybuf[s] (bufs[0])
        int total = bg*n;
        int off = (s == 0) ? 0 : (s == 1 ? M0 : M0 + M1);
        k_head<<<(total*32 + 255)/256, 256>>>(ybuf[s], dgcn_hw + s*64, dgcn_hb + s, g_logitp + off, total);
    }

    // losses + preds
    k_bce<<<1, 256>>>(g_logitp,        target0, out, M0, 0);
    k_bce<<<1, 256>>>(g_logitp + M0,   target1, out, M1, 2);
    k_bce<<<1, 256>>>(g_logitp + M0+M1,target2, out, M2, 4);
    k_preds<<<(3968 + 255)/256, 256>>>(out);
    (void)in_sizes; (void)n_in; (void)out_size;
}

// round 4
// speedup vs baseline: 1.4534x; 1.4534x over previous
#include <cuda_runtime.h>
#include <math.h>

#define BB 2
#define CC 128
#define HH 128
#define WW 128
#define NPIX (HH*WW)
#define HTH 184
#define HTW 180
#define NBINS (HTH*HTW)      // 33120
#define NSPH 16384
#define KHT 8
#define KSPH 16
#define NN0 1024
#define NN1 256
#define NN2 64
#define EPS_F 1e-5f
#define M_CONV (BB*NBINS)    // 66240
#define NCHUNK 240
#define ROWS_PER_CHUNK (M_CONV/NCHUNK)  // 276

// ---------------- scratch (static device memory; no runtime allocation) ----------------
__device__ float g_xt[BB*NPIX*CC];        // post-BN ReLU image, [b][pix][c]
__device__ float g_ht[BB*NBINS*CC];       // hough output, [b][bin][c]
__device__ float g_hc[BB*NBINS*CC];       // conv output
__device__ float g_scale[CC], g_bias[CC];
__device__ float g_cscale[CC], g_cbias[CC];
__device__ float g_psum[NCHUNK*CC], g_psq[NCHUNK*CC];
__device__ float g_s0[BB*NN0*CC], g_s1[BB*3*NN1*CC], g_s2[BB*3*NN2*CC];
__device__ float g_y0[BB*NN0*64], g_y1[BB*3*NN1*64], g_y2[BB*3*NN2*64];
__device__ float g_tmp[BB*NN0*64];
__device__ float g_z[BB*NN0*128];         // EdgeConv GEMM output [zc | yn]
__device__ float g_scs[64], g_scb[64];
__device__ float g_p2s[32*64], g_p2q[32*64];
__device__ float g_logit[BB*NN0 + BB*3*NN1 + BB*3*NN2];

// ---------------- 1) image BN stats ----------------
__global__ void k_img_stats(const float* __restrict__ img,
                            const float* __restrict__ gamma,
                            const float* __restrict__ beta) {
    int c = blockIdx.x;
    float s = 0.f, q = 0.f;
    for (int i = threadIdx.x; i < BB*NPIX; i += blockDim.x) {
        int b = i >> 14;
        int p = i & (NPIX-1);
        float v = img[(b*CC + c)*NPIX + p];
        s += v; q += v*v;
    }
    __shared__ float ss[256], sq[256];
    ss[threadIdx.x] = s; sq[threadIdx.x] = q;
    __syncthreads();
    for (int st = 128; st > 0; st >>= 1) {
        if (threadIdx.x < st) { ss[threadIdx.x] += ss[threadIdx.x+st]; sq[threadIdx.x] += sq[threadIdx.x+st]; }
        __syncthreads();
    }
    if (threadIdx.x == 0) {
        float inv = 1.f/(BB*NPIX);
        float m = ss[0]*inv;
        float var = sq[0]*inv - m*m;
        float r = rsqrtf(var + EPS_F);
        g_scale[c] = gamma[c]*r;
        g_bias[c]  = beta[c] - gamma[c]*m*r;
    }
}

// ---------------- 2) BN + ReLU + transpose ----------------
__global__ void k_bn_transpose(const float* __restrict__ img) {
    __shared__ float tile[32][33];
    int p0 = blockIdx.x*32, c0 = blockIdx.y*32, b = blockIdx.z;
    #pragma unroll
    for (int j = 0; j < 4; j++) {
        int c = c0 + threadIdx.y + j*8;
        tile[threadIdx.y + j*8][threadIdx.x] = img[(b*CC + c)*NPIX + p0 + threadIdx.x];
    }
    __syncthreads();
    #pragma unroll
    for (int j = 0; j < 4; j++) {
        int p = p0 + threadIdx.y + j*8;
        int c = c0 + threadIdx.x;
        float v = g_scale[c]*tile[threadIdx.x][threadIdx.y + j*8] + g_bias[c];
        g_xt[((size_t)b*NPIX + p)*CC + c] = fmaxf(v, 0.f);
    }
}

// ---------------- 3) Hough gather ----------------
__global__ void k_hough(const int* __restrict__ ht_idx, const float* __restrict__ ht_w) {
    int bin = blockIdx.x, b = blockIdx.y, c = threadIdx.x;
    const float* xb = g_xt + (size_t)b*NPIX*CC;
    float acc = 0.f;
    #pragma unroll
    for (int k = 0; k < KHT; k++) {
        int p = __ldg(&ht_idx[bin*KHT + k]);
        float w = __ldg(&ht_w[bin*KHT + k]);
        acc += w * xb[p*CC + c];
    }
    g_ht[((size_t)b*NBINS + bin)*CC + c] = acc;
}

// ---------------- 4) 3x3 conv as implicit GEMM, double-buffered ----------------
#define BM 64
#define BN 128
#define BK 16
#define NCH 72   // 9 taps * (128/BK)
__global__ void __launch_bounds__(256) k_conv(const float* __restrict__ Wt) {
    __shared__ float As[2][BK][BM+4];
    __shared__ float Bs[2][BK][BN];
    int m0 = blockIdx.x*BM;
    int tid = threadIdx.x;
    int tm = (tid >> 4)*4;
    int tn = (tid & 15)*8;
    float acc[4][8];
    #pragma unroll
    for (int i = 0; i < 4; i++)
        #pragma unroll
        for (int j = 0; j < 8; j++) acc[i][j] = 0.f;

    int lm = tid >> 2, lseg = (tid & 3)*4;
    int s  = m0 + lm;
    int sb = s / NBINS; int sr = s - sb*NBINS;
    int sh = sr / HTW;  int sw = sr - sh*HTW;
    int lkb = tid >> 4, lcb = (tid & 15)*8;

    float4 aR, bR0, bR1;
    auto LOAD = [&](int ch) {
        int r = ch >> 3, kk = (ch & 7)*BK;
        int ry = r/3;
        int dy = ry - 1, dx = r - ry*3 - 1;
        int h2 = sh + dy, w2 = sw + dx;
        bool valid = ((unsigned)h2 < HTH) && ((unsigned)w2 < HTW);
        aR = make_float4(0.f,0.f,0.f,0.f);
        if (valid) aR = *(const float4*)(g_ht + (((size_t)sb*NBINS) + h2*HTW + w2)*CC + kk + lseg);
        const float* bp = Wt + ((size_t)r*CC + kk + lkb)*CC + lcb;
        bR0 = *(const float4*)bp;
        bR1 = *(const float4*)(bp + 4);
    };
    auto STORE = [&](int buf) {
        As[buf][lseg+0][lm] = aR.x; As[buf][lseg+1][lm] = aR.y;
        As[buf][lseg+2][lm] = aR.z; As[buf][lseg+3][lm] = aR.w;
        *(float4*)&Bs[buf][lkb][lcb]   = bR0;
        *(float4*)&Bs[buf][lkb][lcb+4] = bR1;
    };

    LOAD(0); STORE(0);
    LOAD(1);
    __syncthreads();
    for (int ch = 0; ch < NCH; ch++) {
        int cur = ch & 1, nxt = cur ^ 1;
        if (ch + 1 < NCH) STORE(nxt);       // regs hold chunk ch+1
        if (ch + 2 < NCH) LOAD(ch + 2);     // overlap global with compute
        #pragma unroll
        for (int k = 0; k < BK; k++) {
            float4 a4 = *(const float4*)&As[cur][k][tm];
            float4 b0 = *(const float4*)&Bs[cur][k][tn];
            float4 b1 = *(const float4*)&Bs[cur][k][tn+4];
            float a[4] = {a4.x, a4.y, a4.z, a4.w};
            float bb[8] = {b0.x,b0.y,b0.z,b0.w,b1.x,b1.y,b1.z,b1.w};
            #pragma unroll
            for (int i = 0; i < 4; i++)
                #pragma unroll
                for (int j = 0; j < 8; j++)
                    acc[i][j] += a[i]*bb[j];
        }
        __syncthreads();
    }
    #pragma unroll
    for (int i = 0; i < 4; i++) {
        size_t m = (size_t)(m0 + tm + i);
        float* cp = g_hc + m*CC + tn;
        *(float4*)cp     = make_float4(acc[i][0],acc[i][1],acc[i][2],acc[i][3]);
        *(float4*)(cp+4) = make_float4(acc[i][4],acc[i][5],acc[i][6],acc[i][7]);
    }
}

// ---------------- 5) conv BN stats ----------------
__global__ void k_conv_stats1() {
    int chunk = blockIdx.x, c = threadIdx.x;
    size_t r0 = (size_t)chunk * ROWS_PER_CHUNK;
    float s = 0.f, q = 0.f;
    for (int i = 0; i < ROWS_PER_CHUNK; i++) {
        float v = g_hc[(r0 + i)*CC + c];
        s += v; q += v*v;
    }
    g_psum[chunk*CC + c] = s;
    g_psq[chunk*CC + c]  = q;
}
__global__ void k_conv_stats2(const float* __restrict__ gamma, const float* __restrict__ beta) {
    int c = threadIdx.x;
    float s = 0.f, q = 0.f;
    for (int i = 0; i < NCHUNK; i++) { s += g_psum[i*CC + c]; q += g_psq[i*CC + c]; }
    float inv = 1.f/(float)M_CONV;
    float m = s*inv;
    float var = q*inv - m*m;
    float r = rsqrtf(var + EPS_F);
    g_cscale[c] = gamma[c]*r;
    g_cbias[c]  = beta[c] - gamma[c]*m*r;
}

// ---------------- 6) sphere gather ----------------
__global__ void k_sphere(const int* __restrict__ ind, const int* __restrict__ sph_idx,
                         const float* __restrict__ sph_w, float* __restrict__ out, int S) {
    int j = blockIdx.x, b = blockIdx.y, c = threadIdx.x;
    int v = __ldg(&ind[b*S + j]);
    const float* hc = g_hc + (size_t)b*NBINS*CC;
    float sc = g_cscale[c], bi = g_cbias[c];
    float acc = 0.f;
    #pragma unroll
    for (int k = 0; k < KSPH; k++) {
        int bin = __ldg(&sph_idx[v*KSPH + k]);
        float w = __ldg(&sph_w[v*KSPH + k]);
        float x = sc*hc[(size_t)bin*CC + c] + bi;
        acc += w * fmaxf(x, 0.f);
    }
    out[((size_t)b*S + j)*CC + c] = acc;
}

// ---------------- 7) sconv: [M,128] @ W[64,128]^T + b ----------------
__global__ void __launch_bounds__(256) k_sconv2(const float* __restrict__ x,
                                                const float* __restrict__ w,
                                                const float* __restrict__ bias,
                                                float* __restrict__ y) {
    __shared__ float Ws[128][64];
    __shared__ float xr[4][128];
    __shared__ float bs[64];
    int tid = threadIdx.x;
    for (int i = tid; i < 64*128; i += 256) {
        int o = i >> 7, c = i & 127;
        Ws[c][o] = w[i];
    }
    if (tid < 64) bs[tid] = bias[tid];
    __syncthreads();
    int ty = tid >> 6, o = tid & 63;
    int m0 = blockIdx.x * 16;
    for (int rr = 0; rr < 16; rr += 4) {
        int m = m0 + rr + ty;
        xr[ty][o]      = x[(size_t)m*128 + o];
        xr[ty][64 + o] = x[(size_t)m*128 + 64 + o];
        __syncthreads();
        float acc = bs[o];
        #pragma unroll 8
        for (int c = 0; c < 128; c++) acc += xr[ty][c]*Ws[c][o];
        y[(size_t)m*64 + o] = acc;
        __syncthreads();
    }
}

// ---------------- 7b) sconv BN stats, chunked ----------------
__global__ void k_sc_stats1(const float* __restrict__ y) {
    int chunk = blockIdx.x, o = threadIdx.x;
    size_t r0 = (size_t)chunk * 64;
    float s = 0.f, q = 0.f;
    for (int i = 0; i < 64; i++) {
        float v = y[(r0 + i)*64 + o];
        s += v; q += v*v;
    }
    g_p2s[chunk*64 + o] = s;
    g_p2q[chunk*64 + o] = q;
}
__global__ void k_sc_stats2(const float* __restrict__ gamma, const float* __restrict__ beta,
                            int nchunk, int M) {
    int o = threadIdx.x;
    float s = 0.f, q = 0.f;
    for (int i = 0; i < nchunk; i++) { s += g_p2s[i*64 + o]; q += g_p2q[i*64 + o]; }
    float inv = 1.f/(float)M;
    float mn = s*inv;
    float var = q*inv - mn*mn;
    float r = rsqrtf(var + EPS_F);
    g_scs[o] = gamma[o]*r;
    g_scb[o] = beta[o] - gamma[o]*mn*r;
}

// ---------------- 8) EdgeConv: GEMM part ----------------
// z[m][0:64]  = x'[m] @ (Wtop - Wbot) + b   (zc)
// z[m][64:128]= x'[m] @ Wbot                (yn)
// where x' = relu(bnsc*x + bnbi) if bnsc != null, else x.
__global__ void __launch_bounds__(256) k_dgcn_gemm(const float* __restrict__ x,
                                                   const float* __restrict__ W,
                                                   const float* __restrict__ bias,
                                                   const float* __restrict__ bnsc,
                                                   const float* __restrict__ bnbi,
                                                   float* __restrict__ z) {
    __shared__ float Wc[64][64];
    __shared__ float Wn[64][64];
    __shared__ float xr[4][64];
    __shared__ float bs[64];
    int tid = threadIdx.x;
    for (int i = tid; i < 64*64; i += 256) {
        int c = i >> 6, o = i & 63;
        float wt = W[c*64 + o], wb = W[(64 + c)*64 + o];
        Wc[c][o] = wt - wb;
        Wn[c][o] = wb;
    }
    if (tid < 64) bs[tid] = bias[tid];
    __syncthreads();
    int ty = tid >> 6, o = tid & 63;
    int m0 = blockIdx.x * 16;
    for (int rr = 0; rr < 16; rr += 4) {
        int m = m0 + rr + ty;
        {
            float v = x[(size_t)m*64 + o];
            if (bnsc) v = fmaxf(bnsc[o]*v + bnbi[o], 0.f);
            xr[ty][o] = v;
        }
        __syncthreads();
        float a0 = bs[o], a1 = 0.f;
        #pragma unroll 8
        for (int c = 0; c < 64; c++) {
            float xv = xr[ty][c];
            a0 += xv * Wc[c][o];
            a1 += xv * Wn[c][o];
        }
        z[(size_t)m*128 + o]      = a0;
        z[(size_t)m*128 + 64 + o] = a1;
        __syncthreads();
    }
}

// ---------------- 8b) EdgeConv: combine part ----------------
// out[j][o] = max_k relu( zc[ci_k][o] + yn[ni_k][o] )
__global__ void k_dgcn_combine(const float* __restrict__ z, const int* __restrict__ edge,
                               float* __restrict__ xo, int n, int kn) {
    int bg = blockIdx.y;
    int o  = threadIdx.x & 63;
    int jy = threadIdx.x >> 6;
    int j  = blockIdx.x*4 + jy;
    const int* ec = edge + (size_t)bg*2*n*kn;
    const int* en = ec + n*kn;
    const float* zb = z + (size_t)bg*n*128;
    int e0 = j*kn;
    float mx = 0.f;   // relu values are >= 0
    for (int kk = 0; kk < kn; kk++) {
        int ci = __ldg(&ec[e0 + kk]);
        int ni = __ldg(&en[e0 + kk]);
        float v = zb[(size_t)ci*128 + o] + zb[(size_t)ni*128 + 64 + o];
        mx = fmaxf(mx, fmaxf(v, 0.f));
    }
    xo[((size_t)bg*n + j)*64 + o] = mx;
}

// ---------------- 9) head ----------------
__global__ void k_head(const float* __restrict__ x, const float* __restrict__ hw,
                       const float* __restrict__ hb, float* __restrict__ logit, int total) {
    int gw = (blockIdx.x*blockDim.x + threadIdx.x) >> 5;
    int lane = threadIdx.x & 31;
    if (gw >= total) return;
    float a = x[(size_t)gw*64 + lane]*hw[lane] + x[(size_t)gw*64 + 32 + lane]*hw[32 + lane];
    #pragma unroll
    for (int s2 = 16; s2 > 0; s2 >>= 1) a += __shfl_down_sync(0xffffffffu, a, s2);
    if (lane == 0) logit[gw] = a + hb[0];
}

// ---------------- 10) BCE ----------------
__global__ void k_bce(const float* __restrict__ logit, const int* __restrict__ target,
                      float* __restrict__ out, int M, int outIdx) {
    float sp = 0.f, sn = 0.f, cp = 0.f, cn = 0.f;
    for (int i = threadIdx.x; i < M; i += 256) {
        float z = logit[i];
        float t = (float)target[i];
        float l = fmaxf(z, 0.f) - z*t + log1pf(expf(-fabsf(z)));
        if (t > 0.5f) { sp += l; cp += 1.f; } else { sn += l; cn += 1.f; }
    }
    __shared__ float r0[256], r1[256], r2[256], r3[256];
    r0[threadIdx.x]=sp; r1[threadIdx.x]=sn; r2[threadIdx.x]=cp; r3[threadIdx.x]=cn;
    __syncthreads();
    for (int st = 128; st > 0; st >>= 1) {
        if (threadIdx.x < st) {
            r0[threadIdx.x]+=r0[threadIdx.x+st]; r1[threadIdx.x]+=r1[threadIdx.x+st];
            r2[threadIdx.x]+=r2[threadIdx.x+st]; r3[threadIdx.x]+=r3[threadIdx.x+st];
        }
        __syncthreads();
    }
    if (threadIdx.x == 0) {
        out[outIdx]   = r0[0] / fmaxf(r2[0], 1.f);
        out[outIdx+1] = r1[0] / fmaxf(r3[0], 1.f);
    }
}

// ---------------- 11) preds ----------------
__global__ void k_preds(float* __restrict__ out) {
    int i = blockIdx.x*blockDim.x + threadIdx.x;
    if (i >= 3968) return;
    float z; int b, col;
    if (i < 2048) {
        b = i >> 10; col = i & 1023;
        z = g_logit[i];
    } else if (i < 3584) {
        int m = i - 2048;
        int bg = m >> 8, j = m & 255;
        b = bg/3; int v = bg - b*3;
        col = 1024 + v*256 + j;
        z = g_logit[2048 + m];
    } else {
        int m = i - 3584;
        int bg = m >> 6, j = m & 63;
        b = bg/3; int v = bg - b*3;
        col = 1792 + v*64 + j;
        z = g_logit[3584 + m];
    }
    out[6 + b*1984 + col] = 1.f/(1.f + expf(-z));
}

// ---------------- launch ----------------
extern "C" void kernel_launch(void* const* d_in, const int* in_sizes, int n_in,
                              void* d_out, int out_size) {
    const float* image     = (const float*)d_in[0];
    const float* bn_gamma  = (const float*)d_in[1];
    const float* bn_beta   = (const float*)d_in[2];
    const int*   ht_idx    = (const int*)  d_in[3];
    const float* ht_w      = (const float*)d_in[4];
    const float* w_htconv  = (const float*)d_in[5];
    const float* htbn_g    = (const float*)d_in[6];
    const float* htbn_b    = (const float*)d_in[7];
    const int*   sph_idx   = (const int*)  d_in[8];
    const float* sph_w     = (const float*)d_in[9];
    const float* w_sc      = (const float*)d_in[10];
    const float* b_sc      = (const float*)d_in[11];
    const float* scbn_g    = (const float*)d_in[12];
    const float* scbn_b    = (const float*)d_in[13];
    const float* dgcn_w    = (const float*)d_in[14];
    const float* dgcn_b    = (const float*)d_in[15];
    const float* dgcn_hw   = (const float*)d_in[16];
    const float* dgcn_hb   = (const float*)d_in[17];
    const int*   ind0      = (const int*)  d_in[18];
    const int*   ind1      = (const int*)  d_in[19];
    const int*   ind2      = (const int*)  d_in[20];
    const int*   edge0     = (const int*)  d_in[21];
    const int*   edge1     = (const int*)  d_in[22];
    const int*   edge2     = (const int*)  d_in[23];
    const int*   target0   = (const int*)  d_in[24];
    const int*   target1   = (const int*)  d_in[25];
    const int*   target2   = (const int*)  d_in[26];
    float* out = (float*)d_out;

    k_img_stats<<<CC, 256>>>(image, bn_gamma, bn_beta);
    k_bn_transpose<<<dim3(NPIX/32, CC/32, BB), dim3(32,8)>>>(image);
    k_hough<<<dim3(NBINS, BB), CC>>>(ht_idx, ht_w);
    k_conv<<<M_CONV/BM, 256>>>(w_htconv);
    k_conv_stats1<<<NCHUNK, CC>>>();
    k_conv_stats2<<<1, CC>>>(htbn_g, htbn_b);

    float* g_s0p; cudaGetSymbolAddress((void**)&g_s0p, g_s0);
    float* g_s1p; cudaGetSymbolAddress((void**)&g_s1p, g_s1);
    float* g_s2p; cudaGetSymbolAddress((void**)&g_s2p, g_s2);
    float* g_y0p; cudaGetSymbolAddress((void**)&g_y0p, g_y0);
    float* g_y1p; cudaGetSymbolAddress((void**)&g_y1p, g_y1);
    float* g_y2p; cudaGetSymbolAddress((void**)&g_y2p, g_y2);
    float* g_tmpp; cudaGetSymbolAddress((void**)&g_tmpp, g_tmp);
    float* g_zp; cudaGetSymbolAddress((void**)&g_zp, g_z);
    float* g_scsp; cudaGetSymbolAddress((void**)&g_scsp, g_scs);
    float* g_scbp; cudaGetSymbolAddress((void**)&g_scbp, g_scb);
    float* g_logitp; cudaGetSymbolAddress((void**)&g_logitp, g_logit);

    k_sphere<<<dim3(NN0,   BB), CC>>>(ind0, sph_idx, sph_w, g_s0p, NN0);
    k_sphere<<<dim3(3*NN1, BB), CC>>>(ind1, sph_idx, sph_w, g_s1p, 3*NN1);
    k_sphere<<<dim3(3*NN2, BB), CC>>>(ind2, sph_idx, sph_w, g_s2p, 3*NN2);

    const int M0 = BB*NN0, M1 = BB*3*NN1, M2 = BB*3*NN2;   // 2048, 1536, 384
    const float* srcS[3] = {g_s0p, g_s1p, g_s2p};
    float* ybuf[3] = {g_y0p, g_y1p, g_y2p};
    const int Ms[3] = {M0, M1, M2};

    for (int s = 0; s < 3; s++) {
        int M = Ms[s];
        k_sconv2<<<M/16, 256>>>(srcS[s], w_sc + (size_t)s*64*128, b_sc + s*64, ybuf[s]);
        k_sc_stats1<<<M/64, 64>>>(ybuf[s]);
        k_sc_stats2<<<1, 64>>>(scbn_g + s*64, scbn_b + s*64, M/64, M);

        int n  = (s == 0) ? NN0 : (s == 1 ? NN1 : NN2);
        int bg = (s == 0) ? BB : BB*3;
        const int* eg = (s == 0) ? edge0 : (s == 1 ? edge1 : edge2);
        // ping-pong: in ybuf -> tmp -> ybuf -> tmp -> ybuf
        float* xin  = ybuf[s];
        for (int L = 0; L < 4; L++) {
            float* xout = (L & 1) ? ybuf[s] : g_tmpp;
            k_dgcn_gemm<<<M/16, 256>>>(xin,
                dgcn_w + ((size_t)s*4 + L)*128*64,
                dgcn_b + ((size_t)s*4 + L)*64,
                (L == 0) ? g_scsp : nullptr,
                (L == 0) ? g_scbp : nullptr,
                g_zp);
            k_dgcn_combine<<<dim3(n/4, bg), 256>>>(g_zp, eg, xout, n, 8);
            xin = xout;
        }
        int off = (s == 0) ? 0 : (s == 1 ? M0 : M0 + M1);
        k_head<<<(M*32 + 255)/256, 256>>>(xin, dgcn_hw + s*64, dgcn_hb + s, g_logitp + off, M);
    }

    k_bce<<<1, 256>>>(g_logitp,          target0, out, M0, 0);
    k_bce<<<1, 256>>>(g_logitp + M0,     target1, out, M1, 2);
    k_bce<<<1, 256>>>(g_logitp + M0+M1,  target2, out, M2, 4);
    k_preds<<<(3968 + 255)/256, 256>>>(out);
    (void)in_sizes; (void)n_in; (void)out_size;
}